// round 14
// baseline (speedup 1.0000x reference)
#include <cuda_runtime.h>
#include <math.h>
#include <stdint.h>

#define TT 4
#define VV 4096
#define EE 4096
#define KK 32
#define DD 8
#define HH 16
#define BERTD 768
#define CATD 784
#define M1 196
#define NROWS (TT * EE)
#define WST 340      // words per kk row of W tile (main 0..315, tail 320..335)

typedef unsigned long long ull;

// ---------------- scratch ----------------
__device__ __align__(256) float g_new_prices[TT * VV * HH];
__device__ __align__(256) float g_he_emb[TT * EE * HH];
__device__ __align__(256) float g_z[TT * EE];
__device__ __align__(256) float g_G[TT * EE * 64];
__device__ __align__(256) float g_gates[TT * VV * 64];
__device__ __align__(256) float g_bias[64];

__device__ __forceinline__ float sigf(float x) { return 1.0f / (1.0f + __expf(-x)); }
__device__ __forceinline__ float tanh_f(float x) {
    float e = __expf(-2.0f * x);
    return (1.0f - e) / (1.0f + e);
}

#define FMA2(d, a, b) asm("fma.rn.f32x2 %0, %1, %2, %0;" : "+l"(d) : "l"(a), "l"(b))
#define UNPACK2(lo, hi, p) asm("mov.b64 {%0, %1}, %2;" : "=f"(lo), "=f"(hi) : "l"(p))
#define DUP2(d, v) asm("mov.b64 %0, {%1, %1};" : "=l"(d) : "f"(v))

// ============================================================================
// K0: tiny bias precompute
// ============================================================================
__global__ void k_prep_bias(const float* __restrict__ bih, const float* __restrict__ bhh) {
    int t = threadIdx.x;
    g_bias[t] = bih[t] + bhh[t];
}

// ============================================================================
// K1 v2: price LSTM — 16 lanes per vertex (verified 8us)
// ============================================================================
__global__ void __launch_bounds__(256) k_price_lstm(
        const float* __restrict__ prices,
        const float* __restrict__ Wih, const float* __restrict__ Whh,
        const float* __restrict__ bih, const float* __restrict__ bhh) {
    __shared__ float sWT[1024];   // [u][j*4+gate]
    __shared__ float sWih[64], sb[64];
    int tid = threadIdx.x;
#pragma unroll
    for (int i = tid; i < 1024; i += 256) {
        int u = i >> 6, r = i & 63;
        int j = r >> 2, g = r & 3;
        sWT[i] = Whh[(g * 16 + j) * 16 + u];
    }
    if (tid < 64) { sWih[tid] = Wih[tid]; sb[tid] = bih[tid] + bhh[tid]; }
    __syncthreads();
    int lane = tid & 31, w = tid >> 5;
    int j = lane & 15, base = lane & 16;
    int v = blockIdx.x * 16 + w * 2 + (lane >> 4);
    float wih_i = sWih[j], wih_f = sWih[16 + j], wih_g = sWih[32 + j], wih_o = sWih[48 + j];
    float b_i = sb[j], b_f = sb[16 + j], b_g = sb[32 + j], b_o = sb[48 + j];
    float h = 0.f, c = 0.f;
#pragma unroll
    for (int t = 0; t < TT; t++) {
        float x = prices[t * VV + v];
        float gi = fmaf(wih_i, x, b_i);
        float gf = fmaf(wih_f, x, b_f);
        float gg = fmaf(wih_g, x, b_g);
        float go = fmaf(wih_o, x, b_o);
#pragma unroll
        for (int u = 0; u < 16; u++) {
            float hv = __shfl_sync(0xffffffffu, h, base + u);
            float4 wv = *(const float4*)&sWT[u * 64 + j * 4];
            gi = fmaf(wv.x, hv, gi);
            gf = fmaf(wv.y, hv, gf);
            gg = fmaf(wv.z, hv, gg);
            go = fmaf(wv.w, hv, go);
        }
        float cn = sigf(gf) * c + sigf(gi) * tanh_f(gg);
        c = cn;
        h = sigf(go) * tanh_f(cn);
        g_new_prices[(t * VV + v) * HH + j] = h;
    }
}

// ============================================================================
// K2 v5: VertexConv — warp = k-row pair, W rows in registers (verified 48us)
// ============================================================================
__global__ void __launch_bounds__(512, 1) k_vertex_conv(
        const int* __restrict__ he_members,
        const float* __restrict__ trans_w, const float* __restrict__ trans_b,
        const float* __restrict__ conv_w, const float* __restrict__ conv_b) {
    extern __shared__ char smv[];
    ull*   regA = (ull*)smv;                       // [16][288]
    float* mlt  = (float*)(smv + 36864);           // [16][1056]
    float* aA   = (float*)(smv + 104448);          // [16][33]
    __shared__ float s_cw[32];
    int tid = threadIdx.x, w = tid >> 5, lane = tid & 31;
    if (tid < 32) s_cw[tid] = conv_w[tid];
    float cb = conv_b[0];

    ull wreg[2][8];
    float tbv[2];
#pragma unroll
    for (int p = 0; p < 2; p++) {
        int m = (w + p * 16) * 32 + lane;
        const float4* src = (const float4*)(trans_w + m * 16);
        float4 v0 = src[0], v1 = src[1], v2 = src[2], v3 = src[3];
        ulonglong2 u0 = *(ulonglong2*)&v0, u1 = *(ulonglong2*)&v1;
        ulonglong2 u2 = *(ulonglong2*)&v2, u3 = *(ulonglong2*)&v3;
        wreg[p][0] = u0.x; wreg[p][1] = u0.y;
        wreg[p][2] = u1.x; wreg[p][3] = u1.y;
        wreg[p][4] = u2.x; wreg[p][5] = u2.y;
        wreg[p][6] = u3.x; wreg[p][7] = u3.y;
        tbv[p] = trans_b[m];
    }

    int ih = blockIdx.x * 16 + w;
    int t = ih >> 12;
    {
        int vidx = he_members[ih * KK + lane];
        const float2* src = (const float2*)(g_new_prices + (t * VV + vidx) * HH);
        ull* rw = regA + w * 288 + lane * 9;
#pragma unroll
        for (int d2 = 0; d2 < 8; d2++) {
            float2 v = src[d2];
            rw[d2] = *(ull*)&v;
        }
    }
    __syncthreads();

#pragma unroll
    for (int p = 0; p < 2; p++) {
        int k = w + p * 16;
#pragma unroll
        for (int e = 0; e < 16; e++) {
            const ull* rr = regA + e * 288 + k * 9;
            ull acc = 0ull;
#pragma unroll
            for (int d2 = 0; d2 < 8; d2++) FMA2(acc, rr[d2], wreg[p][d2]);
            float lo, hi;
            UNPACK2(lo, hi, acc);
            mlt[e * 1056 + k * 33 + lane] = lo + hi + tbv[p];
        }
    }
    __syncthreads();

    {
        int e = w, k = lane;
        float* mrow = mlt + e * 1056 + k * 33;
        float r[32], mx = -1e30f;
#pragma unroll
        for (int j = 0; j < 32; j++) { r[j] = mrow[j]; mx = fmaxf(mx, r[j]); }
        float s = 0.f;
#pragma unroll
        for (int j = 0; j < 32; j++) { r[j] = __expf(r[j] - mx); s += r[j]; }
        float f = s_cw[k] / s;
#pragma unroll
        for (int j = 0; j < 32; j++) mrow[j] = r[j] * f;
    }
    __syncthreads();

    {
        float aj = 0.f;
#pragma unroll
        for (int k = 0; k < 32; k++) aj += mlt[w * 1056 + k * 33 + lane];
        aA[w * 33 + lane] = aj;
    }
    __syncwarp();
    if (lane < 16) {
        const float* regf = (const float*)(regA + w * 288);
        const float* aw = aA + w * 33;
        float acc = cb;
#pragma unroll
        for (int j = 0; j < 32; j++) acc = fmaf(aw[j], regf[j * 18 + lane], acc);
        g_he_emb[ih * HH + lane] = acc;
    }
}

// ============================================================================
// K3 v7: FFMA2 GEMM, row-pair packing, M-TILE 64 / 256 BLOCKS / 2 blocks/SM.
// Single-buffer (measured best), identical inner-loop layout; acc halves to
// 34 ull so two CTAs co-reside (4 warps/SMSP hides barrier+LDS latency).
// Shared: wd [16][340] 21760 | a_s @21760 [16][68] 4352 | sb1 @26112 |
//   sw2 @26896 | zred @27680 [64][17] 4352 -> 32032 total (x2 CTAs = 64KB)
// ============================================================================
__global__ void __launch_bounds__(256, 2) k_he_gemm(
        const float* __restrict__ node_embs,
        const float* __restrict__ W1, const float* __restrict__ Wm,
        const float* __restrict__ b1, const float* __restrict__ w2,
        const float* __restrict__ b2v) {
    extern __shared__ char smg[];
    float* wd   = (float*)smg;               // [16][340]
    float* a_s  = (float*)(smg + 21760);     // [16][68]
    float* sb1  = (float*)(smg + 26112);     // [196]
    float* sw2  = (float*)(smg + 26896);     // [196]
    float* zred = (float*)(smg + 27680);     // [64][17]

    int tid = threadIdx.x;
    int cg = tid & 15, rg = tid >> 4;
    int row0 = blockIdx.x * 64;

    if (tid < M1) { sb1[tid] = b1[tid]; sw2[tid] = w2[tid]; }

    // W staging: 5 float4 slots over 272 rows x 4 float4 (rows >=260 dead)
    const float4* wsrc[5]; uint32_t wbase[5]; int wmode[5];
#pragma unroll
    for (int i = 0; i < 5; i++) {
        int idx4 = tid + 256 * i;
        int m = idx4 >> 2, q = idx4 & 3;
        wmode[i] = (idx4 < 1040) ? 1 : 0;
        const float* s = (m < M1) ? (W1 + (size_t)m * CATD) : (Wm + (size_t)(m - M1) * CATD);
        wsrc[i] = (const float4*)s + q;
        if (m < 256) wbase[i] = (uint32_t)((q * 4) * WST + (m >> 4) * 20 + (m & 15));
        else         wbase[i] = (uint32_t)((q * 4) * WST + 320 + (m - 256));
    }
    // A staging: 1 float4 slot covering 64 rows x 4 float4
    int ar = tid >> 2, aq = tid & 3;
    uint32_t abase = (uint32_t)((aq * 4) * 68 + ar);
    const float4* asrc = (const float4*)(node_embs + (size_t)(row0 + ar) * BERTD) + aq;

    // prefetch chunk 0
    float4 wpre[5], apre;
#pragma unroll
    for (int i = 0; i < 5; i++) {
        wpre[i] = make_float4(0.f, 0.f, 0.f, 0.f);
        if (wmode[i]) wpre[i] = *wsrc[i];
    }
    apre = *((const float4*)(g_he_emb + (size_t)(row0 + ar) * HH) + aq);

    ull acc[2][16], acct[2];
#pragma unroll
    for (int p = 0; p < 2; p++) {
        acct[p] = 0ull;
#pragma unroll
        for (int j = 0; j < 16; j++) acc[p][j] = 0ull;
    }

    for (int ch = 0; ch < 49; ch++) {
#pragma unroll
        for (int i = 0; i < 5; i++) {
            if (wmode[i]) {
                wd[wbase[i]]           = wpre[i].x;
                wd[wbase[i] + WST]     = wpre[i].y;
                wd[wbase[i] + 2 * WST] = wpre[i].z;
                wd[wbase[i] + 3 * WST] = wpre[i].w;
            }
        }
        a_s[abase]       = apre.x;
        a_s[abase + 68]  = apre.y;
        a_s[abase + 136] = apre.z;
        a_s[abase + 204] = apre.w;
        __syncthreads();
        if (ch < 48) {
#pragma unroll
            for (int i = 0; i < 5; i++) {
                if (wmode[i]) { wpre[i] = wsrc[i][4]; wsrc[i] += 4; }
            }
            if (ch == 0) apre = asrc[0];
            else         { apre = asrc[4]; asrc += 4; }
        }
#pragma unroll 4
        for (int kk = 0; kk < 16; kk++) {
            ulonglong2 au = *(const ulonglong2*)(a_s + kk * 68 + rg * 4);
            ull ap0 = au.x, ap1 = au.y;
            const float4* wrow = (const float4*)(wd + kk * WST + cg * 20);
            float4 wa = wrow[0], wb = wrow[1], wc = wrow[2], we = wrow[3];
#define COLFMA(J, WV) { ull wdp_; DUP2(wdp_, WV); \
            FMA2(acc[0][J], ap0, wdp_); FMA2(acc[1][J], ap1, wdp_); }
            COLFMA(0,  wa.x) COLFMA(1,  wa.y) COLFMA(2,  wa.z) COLFMA(3,  wa.w)
            COLFMA(4,  wb.x) COLFMA(5,  wb.y) COLFMA(6,  wb.z) COLFMA(7,  wb.w)
            COLFMA(8,  wc.x) COLFMA(9,  wc.y) COLFMA(10, wc.z) COLFMA(11, wc.w)
            COLFMA(12, we.x) COLFMA(13, we.y) COLFMA(14, we.z) COLFMA(15, we.w)
#undef COLFMA
            float wtl = wd[kk * WST + 320 + cg];
            ull wdt; DUP2(wdt, wtl);
            FMA2(acct[0], ap0, wdt); FMA2(acct[1], ap1, wdt);
        }
        __syncthreads();
    }

    // epilogue: acc[p][j] = (rows rg*4+2p, rg*4+2p+1) x col cg*16+j
    float zp[4];
#pragma unroll
    for (int rr = 0; rr < 4; rr++) zp[rr] = 0.f;
#pragma unroll
    for (int p = 0; p < 2; p++) {
#pragma unroll
        for (int j = 0; j < 16; j++) {
            int c = cg * 16 + j;
            float lo, hi;
            UNPACK2(lo, hi, acc[p][j]);
            if (c < M1) {
                zp[2 * p]     = fmaf(sw2[c], fmaxf(lo + sb1[c], 0.f), zp[2 * p]);
                zp[2 * p + 1] = fmaf(sw2[c], fmaxf(hi + sb1[c], 0.f), zp[2 * p + 1]);
            } else if (c < 260) {
                int r = row0 + rg * 4 + 2 * p;
                g_G[(size_t)r * 64 + (c - M1)]       = lo;
                g_G[(size_t)(r + 1) * 64 + (c - M1)] = hi;
            }
        }
        {
            int c = 256 + cg;
            if (c < 260) {
                float lo, hi;
                UNPACK2(lo, hi, acct[p]);
                int r = row0 + rg * 4 + 2 * p;
                g_G[(size_t)r * 64 + (c - M1)]       = lo;
                g_G[(size_t)(r + 1) * 64 + (c - M1)] = hi;
            }
        }
    }
#pragma unroll
    for (int rr = 0; rr < 4; rr++) zred[(rg * 4 + rr) * 17 + cg] = zp[rr];
    __syncthreads();
    if (tid < 64) {
        float s = b2v[0];
#pragma unroll
        for (int c = 0; c < 16; c++) s += zred[tid * 17 + c];
        g_z[row0 + tid] = s;
    }
}

// ============================================================================
// K4: per-vertex softmax over 8 edges + weighted sum of G rows -> gates.
// ============================================================================
__global__ void __launch_bounds__(256) k_gather_gates(const int* __restrict__ ve) {
    __shared__ float sbias[64];
    int tid = threadIdx.x;
    if (tid < 64) sbias[tid] = g_bias[tid];
    __syncthreads();
    int w = tid >> 5, lane = tid & 31;
    int tv = blockIdx.x * 8 + w;
    int t = tv >> 12;
    int eld = 0;
    if (lane < 8) eld = ve[tv * DD + lane];
    float zld = (lane < 8) ? g_z[t * EE + eld] : 0.f;
    float zv[8]; int ev[8];
#pragma unroll
    for (int d = 0; d < 8; d++) {
        zv[d] = __shfl_sync(0xffffffffu, zld, d);
        ev[d] = __shfl_sync(0xffffffffu, eld, d);
    }
    float mx = zv[0];
#pragma unroll
    for (int d = 1; d < 8; d++) mx = fmaxf(mx, zv[d]);
    float s = 0.f;
#pragma unroll
    for (int d = 0; d < 8; d++) { zv[d] = __expf(zv[d] - mx); s += zv[d]; }
    float inv = 1.f / s;
    float a0 = 0.f, a1 = 0.f;
#pragma unroll
    for (int d = 0; d < 8; d++) {
        const float* gr = g_G + (size_t)(t * EE + ev[d]) * 64;
        float wv = zv[d] * inv;
        a0 = fmaf(wv, gr[lane], a0);
        a1 = fmaf(wv, gr[lane + 32], a1);
    }
    g_gates[(size_t)tv * 64 + lane]      = a0 + sbias[lane];
    g_gates[(size_t)tv * 64 + lane + 32] = a1 + sbias[lane + 32];
}

// ============================================================================
// K5 v2: second LSTM + residual + attention + FC — 16 lanes per vertex
// ============================================================================
__global__ void __launch_bounds__(256) k_final(
        const float* __restrict__ Whh,
        const float* __restrict__ attn_in, const float* __restrict__ attn_out,
        const float* __restrict__ fc_w, const float* __restrict__ fc_b,
        float* __restrict__ out) {
    __shared__ float sWT[1024];     // [u][j*4+gate]
    __shared__ float sAinT[256];    // [u][j]
    __shared__ float sAoutT[512];   // [u(32)][j]
    __shared__ float sFc[32], sFcb[2];
    int tid = threadIdx.x;
#pragma unroll
    for (int i = tid; i < 1024; i += 256) {
        int u = i >> 6, r = i & 63;
        int j = r >> 2, g = r & 3;
        sWT[i] = Whh[(g * 16 + j) * 16 + u];
    }
    if (tid < 256) {
        int u = tid >> 4, j = tid & 15;
        sAinT[tid] = attn_in[j * 16 + u];
    }
#pragma unroll
    for (int i = tid; i < 512; i += 256) {
        int u = i >> 4, j = i & 15;
        sAoutT[i] = attn_out[j * 32 + u];
    }
    if (tid < 32) sFc[tid] = fc_w[tid];
    if (tid < 2) sFcb[tid] = fc_b[tid];
    __syncthreads();
    int lane = tid & 31, w = tid >> 5;
    int j = lane & 15, base = lane & 16;
    int v = blockIdx.x * 16 + w * 2 + (lane >> 4);
    float h = 0.f, c = 0.f, la[4];
#pragma unroll
    for (int t = 0; t < 4; t++) {
        size_t gb = (size_t)(t * VV + v) * 64;
        float gi = g_gates[gb + j];
        float gf = g_gates[gb + 16 + j];
        float gg = g_gates[gb + 32 + j];
        float go = g_gates[gb + 48 + j];
#pragma unroll
        for (int u = 0; u < 16; u++) {
            float hv = __shfl_sync(0xffffffffu, h, base + u);
            float4 wv = *(const float4*)&sWT[u * 64 + j * 4];
            gi = fmaf(wv.x, hv, gi);
            gf = fmaf(wv.y, hv, gf);
            gg = fmaf(wv.z, hv, gg);
            go = fmaf(wv.w, hv, go);
        }
        float cn = sigf(gf) * c + sigf(gi) * tanh_f(gg);
        c = cn;
        h = sigf(go) * tanh_f(cn);
        la[t] = h + g_new_prices[(t * VV + v) * HH + j];
    }
    float q = 0.f;
#pragma unroll
    for (int u = 0; u < 16; u++) {
        float la3u = __shfl_sync(0xffffffffu, la[3], base + u);
        q = fmaf(sAinT[u * 16 + j], la3u, q);
    }
    float sc[4];
#pragma unroll
    for (int t = 0; t < 4; t++) {
        float p = q * la[t];
#pragma unroll
        for (int m = 8; m; m >>= 1) p += __shfl_xor_sync(0xffffffffu, p, m);
        sc[t] = p;
    }
    float mx = fmaxf(fmaxf(sc[0], sc[1]), fmaxf(sc[2], sc[3]));
    float ssum = 0.f;
#pragma unroll
    for (int t = 0; t < 4; t++) { sc[t] = __expf(sc[t] - mx); ssum += sc[t]; }
    float inv = 1.f / ssum;
    float mix = 0.f;
#pragma unroll
    for (int t = 0; t < 4; t++) mix = fmaf(sc[t] * inv, la[t], mix);
    float a = 0.f;
#pragma unroll
    for (int u = 0; u < 16; u++) {
        float mu = __shfl_sync(0xffffffffu, mix, base + u);
        float qu = __shfl_sync(0xffffffffu, q, base + u);
        a = fmaf(sAoutT[u * 16 + j], mu, a);
        a = fmaf(sAoutT[(16 + u) * 16 + j], qu, a);
    }
    float attnj = tanh_f(a);
    float p0 = sFc[j] * attnj, p1 = sFc[16 + j] * attnj;
#pragma unroll
    for (int m = 8; m; m >>= 1) {
        p0 += __shfl_xor_sync(0xffffffffu, p0, m);
        p1 += __shfl_xor_sync(0xffffffffu, p1, m);
    }
    if (j == 0) {
        out[v * 2]     = p0 + sFcb[0];
        out[v * 2 + 1] = p1 + sFcb[1];
    }
}

// ============================================================================
extern "C" void kernel_launch(void* const* d_in, const int* in_sizes, int n_in,
                              void* d_out, int out_size) {
    const float* prices = (const float*)d_in[0];
    const float* node   = (const float*)d_in[1];
    const int*   he_mem = (const int*)d_in[2];
    const int*   ve     = (const int*)d_in[3];
    const float* Wih_p  = (const float*)d_in[4];
    const float* Whh_p  = (const float*)d_in[5];
    const float* bih_p  = (const float*)d_in[6];
    const float* bhh_p  = (const float*)d_in[7];
    const float* Wih_m  = (const float*)d_in[8];
    const float* Whh_m  = (const float*)d_in[9];
    const float* bih_m  = (const float*)d_in[10];
    const float* bhh_m  = (const float*)d_in[11];
    const float* tw     = (const float*)d_in[12];
    const float* tb     = (const float*)d_in[13];
    const float* cw     = (const float*)d_in[14];
    const float* cbv    = (const float*)d_in[15];
    const float* w1     = (const float*)d_in[16];
    const float* b1     = (const float*)d_in[17];
    const float* w2     = (const float*)d_in[18];
    const float* b2     = (const float*)d_in[19];
    const float* ain    = (const float*)d_in[20];
    const float* aout   = (const float*)d_in[21];
    const float* fcw    = (const float*)d_in[22];
    const float* fcb    = (const float*)d_in[23];
    float* out = (float*)d_out;
    (void)in_sizes; (void)n_in; (void)out_size;

    const int smem_vc = 106560;
    const int smem_ge = 32032;
    cudaFuncSetAttribute(k_vertex_conv, cudaFuncAttributeMaxDynamicSharedMemorySize, smem_vc);
    cudaFuncSetAttribute(k_he_gemm, cudaFuncAttributeMaxDynamicSharedMemorySize, smem_ge);

    k_prep_bias<<<1, 64>>>(bih_m, bhh_m);                                   // 0
    k_price_lstm<<<VV / 16, 256>>>(prices, Wih_p, Whh_p, bih_p, bhh_p);     // 1
    k_vertex_conv<<<TT * EE / 16, 512, smem_vc>>>(he_mem, tw, tb, cw, cbv); // 2
    k_he_gemm<<<NROWS / 64, 256, smem_ge>>>(node, w1, Wih_m, b1, w2, b2);   // 3 <- profiled
    k_gather_gates<<<TT * VV / 8, 256>>>(ve);                               // 4
    k_final<<<VV / 16, 256>>>(Whh_m, ain, aout, fcw, fcb, out);             // 5
}

// round 15
// speedup vs baseline: 1.1911x; 1.1911x over previous
#include <cuda_runtime.h>
#include <math.h>
#include <stdint.h>

#define TT 4
#define VV 4096
#define EE 4096
#define KK 32
#define DD 8
#define HH 16
#define BERTD 768
#define CATD 784
#define M1 196
#define NROWS (TT * EE)
#define WST 340      // words per kk row of W tile (main 0..315, tail 320..335)

typedef unsigned long long ull;

// ---------------- scratch ----------------
__device__ __align__(256) float g_new_prices[TT * VV * HH];
__device__ __align__(256) float g_he_emb[TT * EE * HH];
__device__ __align__(256) float g_z[TT * EE];
__device__ __align__(256) float g_G[TT * EE * 64];
__device__ __align__(256) float g_gates[TT * VV * 64];
__device__ __align__(256) float g_bias[64];

__device__ __forceinline__ float sigf(float x) { return 1.0f / (1.0f + __expf(-x)); }
__device__ __forceinline__ float tanh_f(float x) {
    float e = __expf(-2.0f * x);
    return (1.0f - e) / (1.0f + e);
}

#define FMA2(d, a, b) asm("fma.rn.f32x2 %0, %1, %2, %0;" : "+l"(d) : "l"(a), "l"(b))
#define UNPACK2(lo, hi, p) asm("mov.b64 {%0, %1}, %2;" : "=f"(lo), "=f"(hi) : "l"(p))
#define DUP2(d, v) asm("mov.b64 %0, {%1, %1};" : "=l"(d) : "f"(v))

// ============================================================================
// K0: tiny bias precompute
// ============================================================================
__global__ void k_prep_bias(const float* __restrict__ bih, const float* __restrict__ bhh) {
    int t = threadIdx.x;
    g_bias[t] = bih[t] + bhh[t];
}

// ============================================================================
// K1 v2: price LSTM — 16 lanes per vertex (verified 8us)
// ============================================================================
__global__ void __launch_bounds__(256) k_price_lstm(
        const float* __restrict__ prices,
        const float* __restrict__ Wih, const float* __restrict__ Whh,
        const float* __restrict__ bih, const float* __restrict__ bhh) {
    __shared__ float sWT[1024];   // [u][j*4+gate]
    __shared__ float sWih[64], sb[64];
    int tid = threadIdx.x;
#pragma unroll
    for (int i = tid; i < 1024; i += 256) {
        int u = i >> 6, r = i & 63;
        int j = r >> 2, g = r & 3;
        sWT[i] = Whh[(g * 16 + j) * 16 + u];
    }
    if (tid < 64) { sWih[tid] = Wih[tid]; sb[tid] = bih[tid] + bhh[tid]; }
    __syncthreads();
    int lane = tid & 31, w = tid >> 5;
    int j = lane & 15, base = lane & 16;
    int v = blockIdx.x * 16 + w * 2 + (lane >> 4);
    float wih_i = sWih[j], wih_f = sWih[16 + j], wih_g = sWih[32 + j], wih_o = sWih[48 + j];
    float b_i = sb[j], b_f = sb[16 + j], b_g = sb[32 + j], b_o = sb[48 + j];
    float h = 0.f, c = 0.f;
#pragma unroll
    for (int t = 0; t < TT; t++) {
        float x = prices[t * VV + v];
        float gi = fmaf(wih_i, x, b_i);
        float gf = fmaf(wih_f, x, b_f);
        float gg = fmaf(wih_g, x, b_g);
        float go = fmaf(wih_o, x, b_o);
#pragma unroll
        for (int u = 0; u < 16; u++) {
            float hv = __shfl_sync(0xffffffffu, h, base + u);
            float4 wv = *(const float4*)&sWT[u * 64 + j * 4];
            gi = fmaf(wv.x, hv, gi);
            gf = fmaf(wv.y, hv, gf);
            gg = fmaf(wv.z, hv, gg);
            go = fmaf(wv.w, hv, go);
        }
        float cn = sigf(gf) * c + sigf(gi) * tanh_f(gg);
        c = cn;
        h = sigf(go) * tanh_f(cn);
        g_new_prices[(t * VV + v) * HH + j] = h;
    }
}

// ============================================================================
// K2 v5: VertexConv — warp = k-row pair, W rows in registers (verified 48us)
// ============================================================================
__global__ void __launch_bounds__(512, 1) k_vertex_conv(
        const int* __restrict__ he_members,
        const float* __restrict__ trans_w, const float* __restrict__ trans_b,
        const float* __restrict__ conv_w, const float* __restrict__ conv_b) {
    extern __shared__ char smv[];
    ull*   regA = (ull*)smv;                       // [16][288]
    float* mlt  = (float*)(smv + 36864);           // [16][1056]
    float* aA   = (float*)(smv + 104448);          // [16][33]
    __shared__ float s_cw[32];
    int tid = threadIdx.x, w = tid >> 5, lane = tid & 31;
    if (tid < 32) s_cw[tid] = conv_w[tid];
    float cb = conv_b[0];

    ull wreg[2][8];
    float tbv[2];
#pragma unroll
    for (int p = 0; p < 2; p++) {
        int m = (w + p * 16) * 32 + lane;
        const float4* src = (const float4*)(trans_w + m * 16);
        float4 v0 = src[0], v1 = src[1], v2 = src[2], v3 = src[3];
        ulonglong2 u0 = *(ulonglong2*)&v0, u1 = *(ulonglong2*)&v1;
        ulonglong2 u2 = *(ulonglong2*)&v2, u3 = *(ulonglong2*)&v3;
        wreg[p][0] = u0.x; wreg[p][1] = u0.y;
        wreg[p][2] = u1.x; wreg[p][3] = u1.y;
        wreg[p][4] = u2.x; wreg[p][5] = u2.y;
        wreg[p][6] = u3.x; wreg[p][7] = u3.y;
        tbv[p] = trans_b[m];
    }

    int ih = blockIdx.x * 16 + w;
    int t = ih >> 12;
    {
        int vidx = he_members[ih * KK + lane];
        const float2* src = (const float2*)(g_new_prices + (t * VV + vidx) * HH);
        ull* rw = regA + w * 288 + lane * 9;
#pragma unroll
        for (int d2 = 0; d2 < 8; d2++) {
            float2 v = src[d2];
            rw[d2] = *(ull*)&v;
        }
    }
    __syncthreads();

#pragma unroll
    for (int p = 0; p < 2; p++) {
        int k = w + p * 16;
#pragma unroll
        for (int e = 0; e < 16; e++) {
            const ull* rr = regA + e * 288 + k * 9;
            ull acc = 0ull;
#pragma unroll
            for (int d2 = 0; d2 < 8; d2++) FMA2(acc, rr[d2], wreg[p][d2]);
            float lo, hi;
            UNPACK2(lo, hi, acc);
            mlt[e * 1056 + k * 33 + lane] = lo + hi + tbv[p];
        }
    }
    __syncthreads();

    {
        int e = w, k = lane;
        float* mrow = mlt + e * 1056 + k * 33;
        float r[32], mx = -1e30f;
#pragma unroll
        for (int j = 0; j < 32; j++) { r[j] = mrow[j]; mx = fmaxf(mx, r[j]); }
        float s = 0.f;
#pragma unroll
        for (int j = 0; j < 32; j++) { r[j] = __expf(r[j] - mx); s += r[j]; }
        float f = s_cw[k] / s;
#pragma unroll
        for (int j = 0; j < 32; j++) mrow[j] = r[j] * f;
    }
    __syncthreads();

    {
        float aj = 0.f;
#pragma unroll
        for (int k = 0; k < 32; k++) aj += mlt[w * 1056 + k * 33 + lane];
        aA[w * 33 + lane] = aj;
    }
    __syncwarp();
    if (lane < 16) {
        const float* regf = (const float*)(regA + w * 288);
        const float* aw = aA + w * 33;
        float acc = cb;
#pragma unroll
        for (int j = 0; j < 32; j++) acc = fmaf(aw[j], regf[j * 18 + lane], acc);
        g_he_emb[ih * HH + lane] = acc;
    }
}

// ============================================================================
// K3 (R12-measured-best): FFMA2 GEMM, row-pair packing, M-tile 128,
// 256 threads, 8 rows/thread, single buffer. Only change: kk unroll 8.
// Shared: wd [16][340] 21760 | a_s @21760 [16][132] 8448 | sb1 @30208 |
//   sw2 @30992 | zred @31776 [128][17] 8704 -> 40480 total
// ============================================================================
__global__ void __launch_bounds__(256, 1) k_he_gemm(
        const float* __restrict__ node_embs,
        const float* __restrict__ W1, const float* __restrict__ Wm,
        const float* __restrict__ b1, const float* __restrict__ w2,
        const float* __restrict__ b2v) {
    extern __shared__ char smg[];
    float* wd   = (float*)smg;               // [16][340]
    float* a_s  = (float*)(smg + 21760);     // [16][132]
    float* sb1  = (float*)(smg + 30208);     // [196]
    float* sw2  = (float*)(smg + 30992);     // [196]
    float* zred = (float*)(smg + 31776);     // [128][17]

    int tid = threadIdx.x;
    int cg = tid & 15, rg = tid >> 4;
    int row0 = blockIdx.x * 128;

    if (tid < M1) { sb1[tid] = b1[tid]; sw2[tid] = w2[tid]; }

    const float4* wsrc[5]; uint32_t wbase[5]; int wmode[5];
#pragma unroll
    for (int i = 0; i < 5; i++) {
        int idx4 = tid + 256 * i;
        int m = idx4 >> 2, q = idx4 & 3;
        wmode[i] = (idx4 < 1040) ? 1 : 0;
        const float* s = (m < M1) ? (W1 + (size_t)m * CATD) : (Wm + (size_t)(m - M1) * CATD);
        wsrc[i] = (const float4*)s + q;
        if (m < 256) wbase[i] = (uint32_t)((q * 4) * WST + (m >> 4) * 20 + (m & 15));
        else         wbase[i] = (uint32_t)((q * 4) * WST + 320 + (m - 256));
    }
    const float4* asrc[2]; uint32_t abase[2];
#pragma unroll
    for (int i = 0; i < 2; i++) {
        int idx4 = tid + 256 * i;
        int r = idx4 >> 2, q = idx4 & 3;
        abase[i] = (uint32_t)((q * 4) * 132 + r);
        asrc[i] = (const float4*)(node_embs + (size_t)(row0 + r) * BERTD) + q;
    }

    float4 wpre[5], apre[2];
#pragma unroll
    for (int i = 0; i < 5; i++) {
        wpre[i] = make_float4(0.f, 0.f, 0.f, 0.f);
        if (wmode[i]) wpre[i] = *wsrc[i];
    }
#pragma unroll
    for (int i = 0; i < 2; i++) {
        int idx4 = tid + 256 * i;
        int r = idx4 >> 2, q = idx4 & 3;
        apre[i] = *((const float4*)(g_he_emb + (size_t)(row0 + r) * HH) + q);
    }

    ull acc[4][16], acct[4];
#pragma unroll
    for (int p = 0; p < 4; p++) {
        acct[p] = 0ull;
#pragma unroll
        for (int j = 0; j < 16; j++) acc[p][j] = 0ull;
    }

    for (int ch = 0; ch < 49; ch++) {
#pragma unroll
        for (int i = 0; i < 5; i++) {
            if (wmode[i]) {
                wd[wbase[i]]           = wpre[i].x;
                wd[wbase[i] + WST]     = wpre[i].y;
                wd[wbase[i] + 2 * WST] = wpre[i].z;
                wd[wbase[i] + 3 * WST] = wpre[i].w;
            }
        }
#pragma unroll
        for (int i = 0; i < 2; i++) {
            a_s[abase[i]]       = apre[i].x;
            a_s[abase[i] + 132] = apre[i].y;
            a_s[abase[i] + 264] = apre[i].z;
            a_s[abase[i] + 396] = apre[i].w;
        }
        __syncthreads();
        if (ch < 48) {
#pragma unroll
            for (int i = 0; i < 5; i++) {
                if (wmode[i]) { wpre[i] = wsrc[i][4]; wsrc[i] += 4; }
            }
            if (ch == 0) {
#pragma unroll
                for (int i = 0; i < 2; i++) apre[i] = asrc[i][0];
            } else {
#pragma unroll
                for (int i = 0; i < 2; i++) { apre[i] = asrc[i][4]; asrc[i] += 4; }
            }
        }
#pragma unroll 8
        for (int kk = 0; kk < 16; kk++) {
            const float* ab = a_s + kk * 132 + rg * 8;
            ulonglong2 au0 = *(const ulonglong2*)ab;
            ulonglong2 au1 = *(const ulonglong2*)(ab + 4);
            ull ap0 = au0.x, ap1 = au0.y, ap2 = au1.x, ap3 = au1.y;
            const float4* wrow = (const float4*)(wd + kk * WST + cg * 20);
            float4 wa = wrow[0], wb = wrow[1], wc = wrow[2], we = wrow[3];
#define COLFMA(J, WV) { ull wdp_; DUP2(wdp_, WV); \
            FMA2(acc[0][J], ap0, wdp_); FMA2(acc[1][J], ap1, wdp_); \
            FMA2(acc[2][J], ap2, wdp_); FMA2(acc[3][J], ap3, wdp_); }
            COLFMA(0,  wa.x) COLFMA(1,  wa.y) COLFMA(2,  wa.z) COLFMA(3,  wa.w)
            COLFMA(4,  wb.x) COLFMA(5,  wb.y) COLFMA(6,  wb.z) COLFMA(7,  wb.w)
            COLFMA(8,  wc.x) COLFMA(9,  wc.y) COLFMA(10, wc.z) COLFMA(11, wc.w)
            COLFMA(12, we.x) COLFMA(13, we.y) COLFMA(14, we.z) COLFMA(15, we.w)
#undef COLFMA
            float wtl = wd[kk * WST + 320 + cg];
            ull wdt; DUP2(wdt, wtl);
            FMA2(acct[0], ap0, wdt); FMA2(acct[1], ap1, wdt);
            FMA2(acct[2], ap2, wdt); FMA2(acct[3], ap3, wdt);
        }
        __syncthreads();
    }

    float zp[8];
#pragma unroll
    for (int rr = 0; rr < 8; rr++) zp[rr] = 0.f;
#pragma unroll
    for (int p = 0; p < 4; p++) {
#pragma unroll
        for (int j = 0; j < 16; j++) {
            int c = cg * 16 + j;
            float lo, hi;
            UNPACK2(lo, hi, acc[p][j]);
            if (c < M1) {
                zp[2 * p]     = fmaf(sw2[c], fmaxf(lo + sb1[c], 0.f), zp[2 * p]);
                zp[2 * p + 1] = fmaf(sw2[c], fmaxf(hi + sb1[c], 0.f), zp[2 * p + 1]);
            } else if (c < 260) {
                int r = row0 + rg * 8 + 2 * p;
                g_G[(size_t)r * 64 + (c - M1)]       = lo;
                g_G[(size_t)(r + 1) * 64 + (c - M1)] = hi;
            }
        }
        {
            int c = 256 + cg;
            if (c < 260) {
                float lo, hi;
                UNPACK2(lo, hi, acct[p]);
                int r = row0 + rg * 8 + 2 * p;
                g_G[(size_t)r * 64 + (c - M1)]       = lo;
                g_G[(size_t)(r + 1) * 64 + (c - M1)] = hi;
            }
        }
    }
#pragma unroll
    for (int rr = 0; rr < 8; rr++) zred[(rg * 8 + rr) * 17 + cg] = zp[rr];
    __syncthreads();
    if (tid < 128) {
        float s = b2v[0];
#pragma unroll
        for (int c = 0; c < 16; c++) s += zred[tid * 17 + c];
        g_z[row0 + tid] = s;
    }
}

// ============================================================================
// K4: per-vertex softmax over 8 edges + weighted sum of G rows -> gates.
// ============================================================================
__global__ void __launch_bounds__(256) k_gather_gates(const int* __restrict__ ve) {
    __shared__ float sbias[64];
    int tid = threadIdx.x;
    if (tid < 64) sbias[tid] = g_bias[tid];
    __syncthreads();
    int w = tid >> 5, lane = tid & 31;
    int tv = blockIdx.x * 8 + w;
    int t = tv >> 12;
    int eld = 0;
    if (lane < 8) eld = ve[tv * DD + lane];
    float zld = (lane < 8) ? g_z[t * EE + eld] : 0.f;
    float zv[8]; int ev[8];
#pragma unroll
    for (int d = 0; d < 8; d++) {
        zv[d] = __shfl_sync(0xffffffffu, zld, d);
        ev[d] = __shfl_sync(0xffffffffu, eld, d);
    }
    float mx = zv[0];
#pragma unroll
    for (int d = 1; d < 8; d++) mx = fmaxf(mx, zv[d]);
    float s = 0.f;
#pragma unroll
    for (int d = 0; d < 8; d++) { zv[d] = __expf(zv[d] - mx); s += zv[d]; }
    float inv = 1.f / s;
    float a0 = 0.f, a1 = 0.f;
#pragma unroll
    for (int d = 0; d < 8; d++) {
        const float* gr = g_G + (size_t)(t * EE + ev[d]) * 64;
        float wv = zv[d] * inv;
        a0 = fmaf(wv, gr[lane], a0);
        a1 = fmaf(wv, gr[lane + 32], a1);
    }
    g_gates[(size_t)tv * 64 + lane]      = a0 + sbias[lane];
    g_gates[(size_t)tv * 64 + lane + 32] = a1 + sbias[lane + 32];
}

// ============================================================================
// K5 v2: second LSTM + residual + attention + FC — 16 lanes per vertex
// ============================================================================
__global__ void __launch_bounds__(256) k_final(
        const float* __restrict__ Whh,
        const float* __restrict__ attn_in, const float* __restrict__ attn_out,
        const float* __restrict__ fc_w, const float* __restrict__ fc_b,
        float* __restrict__ out) {
    __shared__ float sWT[1024];     // [u][j*4+gate]
    __shared__ float sAinT[256];    // [u][j]
    __shared__ float sAoutT[512];   // [u(32)][j]
    __shared__ float sFc[32], sFcb[2];
    int tid = threadIdx.x;
#pragma unroll
    for (int i = tid; i < 1024; i += 256) {
        int u = i >> 6, r = i & 63;
        int j = r >> 2, g = r & 3;
        sWT[i] = Whh[(g * 16 + j) * 16 + u];
    }
    if (tid < 256) {
        int u = tid >> 4, j = tid & 15;
        sAinT[tid] = attn_in[j * 16 + u];
    }
#pragma unroll
    for (int i = tid; i < 512; i += 256) {
        int u = i >> 4, j = i & 15;
        sAoutT[i] = attn_out[j * 32 + u];
    }
    if (tid < 32) sFc[tid] = fc_w[tid];
    if (tid < 2) sFcb[tid] = fc_b[tid];
    __syncthreads();
    int lane = tid & 31, w = tid >> 5;
    int j = lane & 15, base = lane & 16;
    int v = blockIdx.x * 16 + w * 2 + (lane >> 4);
    float h = 0.f, c = 0.f, la[4];
#pragma unroll
    for (int t = 0; t < 4; t++) {
        size_t gb = (size_t)(t * VV + v) * 64;
        float gi = g_gates[gb + j];
        float gf = g_gates[gb + 16 + j];
        float gg = g_gates[gb + 32 + j];
        float go = g_gates[gb + 48 + j];
#pragma unroll
        for (int u = 0; u < 16; u++) {
            float hv = __shfl_sync(0xffffffffu, h, base + u);
            float4 wv = *(const float4*)&sWT[u * 64 + j * 4];
            gi = fmaf(wv.x, hv, gi);
            gf = fmaf(wv.y, hv, gf);
            gg = fmaf(wv.z, hv, gg);
            go = fmaf(wv.w, hv, go);
        }
        float cn = sigf(gf) * c + sigf(gi) * tanh_f(gg);
        c = cn;
        h = sigf(go) * tanh_f(cn);
        la[t] = h + g_new_prices[(t * VV + v) * HH + j];
    }
    float q = 0.f;
#pragma unroll
    for (int u = 0; u < 16; u++) {
        float la3u = __shfl_sync(0xffffffffu, la[3], base + u);
        q = fmaf(sAinT[u * 16 + j], la3u, q);
    }
    float sc[4];
#pragma unroll
    for (int t = 0; t < 4; t++) {
        float p = q * la[t];
#pragma unroll
        for (int m = 8; m; m >>= 1) p += __shfl_xor_sync(0xffffffffu, p, m);
        sc[t] = p;
    }
    float mx = fmaxf(fmaxf(sc[0], sc[1]), fmaxf(sc[2], sc[3]));
    float ssum = 0.f;
#pragma unroll
    for (int t = 0; t < 4; t++) { sc[t] = __expf(sc[t] - mx); ssum += sc[t]; }
    float inv = 1.f / ssum;
    float mix = 0.f;
#pragma unroll
    for (int t = 0; t < 4; t++) mix = fmaf(sc[t] * inv, la[t], mix);
    float a = 0.f;
#pragma unroll
    for (int u = 0; u < 16; u++) {
        float mu = __shfl_sync(0xffffffffu, mix, base + u);
        float qu = __shfl_sync(0xffffffffu, q, base + u);
        a = fmaf(sAoutT[u * 16 + j], mu, a);
        a = fmaf(sAoutT[(16 + u) * 16 + j], qu, a);
    }
    float attnj = tanh_f(a);
    float p0 = sFc[j] * attnj, p1 = sFc[16 + j] * attnj;
#pragma unroll
    for (int m = 8; m; m >>= 1) {
        p0 += __shfl_xor_sync(0xffffffffu, p0, m);
        p1 += __shfl_xor_sync(0xffffffffu, p1, m);
    }
    if (j == 0) {
        out[v * 2]     = p0 + sFcb[0];
        out[v * 2 + 1] = p1 + sFcb[1];
    }
}

// ============================================================================
extern "C" void kernel_launch(void* const* d_in, const int* in_sizes, int n_in,
                              void* d_out, int out_size) {
    const float* prices = (const float*)d_in[0];
    const float* node   = (const float*)d_in[1];
    const int*   he_mem = (const int*)d_in[2];
    const int*   ve     = (const int*)d_in[3];
    const float* Wih_p  = (const float*)d_in[4];
    const float* Whh_p  = (const float*)d_in[5];
    const float* bih_p  = (const float*)d_in[6];
    const float* bhh_p  = (const float*)d_in[7];
    const float* Wih_m  = (const float*)d_in[8];
    const float* Whh_m  = (const float*)d_in[9];
    const float* bih_m  = (const float*)d_in[10];
    const float* bhh_m  = (const float*)d_in[11];
    const float* tw     = (const float*)d_in[12];
    const float* tb     = (const float*)d_in[13];
    const float* cw     = (const float*)d_in[14];
    const float* cbv    = (const float*)d_in[15];
    const float* w1     = (const float*)d_in[16];
    const float* b1     = (const float*)d_in[17];
    const float* w2     = (const float*)d_in[18];
    const float* b2     = (const float*)d_in[19];
    const float* ain    = (const float*)d_in[20];
    const float* aout   = (const float*)d_in[21];
    const float* fcw    = (const float*)d_in[22];
    const float* fcb    = (const float*)d_in[23];
    float* out = (float*)d_out;
    (void)in_sizes; (void)n_in; (void)out_size;

    const int smem_vc = 106560;
    const int smem_ge = 40480;
    cudaFuncSetAttribute(k_vertex_conv, cudaFuncAttributeMaxDynamicSharedMemorySize, smem_vc);
    cudaFuncSetAttribute(k_he_gemm, cudaFuncAttributeMaxDynamicSharedMemorySize, smem_ge);

    k_prep_bias<<<1, 64>>>(bih_m, bhh_m);                                   // 0
    k_price_lstm<<<VV / 16, 256>>>(prices, Wih_p, Whh_p, bih_p, bhh_p);     // 1
    k_vertex_conv<<<TT * EE / 16, 512, smem_vc>>>(he_mem, tw, tb, cw, cbv); // 2
    k_he_gemm<<<NROWS / 128, 256, smem_ge>>>(node, w1, Wih_m, b1, w2, b2);  // 3 <- profiled
    k_gather_gates<<<TT * VV / 8, 256>>>(ve);                               // 4
    k_final<<<VV / 16, 256>>>(Whh_m, ain, aout, fcw, fcb, out);             // 5
}

// round 16
// speedup vs baseline: 1.1985x; 1.0061x over previous
#include <cuda_runtime.h>
#include <math.h>
#include <stdint.h>

#define TT 4
#define VV 4096
#define EE 4096
#define KK 32
#define DD 8
#define HH 16
#define BERTD 768
#define CATD 784
#define M1 196
#define NROWS (TT * EE)
#define WST 340      // words per kk row of W tile (main 0..315, tail 320..335)

typedef unsigned long long ull;

// ---------------- scratch ----------------
__device__ __align__(256) float g_new_prices[TT * VV * HH];
__device__ __align__(256) float g_he_emb[TT * EE * HH];
__device__ __align__(256) float g_z[TT * EE];
__device__ __align__(256) float g_G[TT * EE * 64];
__device__ __align__(256) float g_gates[TT * VV * 64];
__device__ __align__(256) float g_bias[64];

__device__ __forceinline__ float sigf(float x) { return 1.0f / (1.0f + __expf(-x)); }
__device__ __forceinline__ float tanh_f(float x) {
    float e = __expf(-2.0f * x);
    return (1.0f - e) / (1.0f + e);
}

#define FMA2(d, a, b) asm("fma.rn.f32x2 %0, %1, %2, %0;" : "+l"(d) : "l"(a), "l"(b))
#define UNPACK2(lo, hi, p) asm("mov.b64 {%0, %1}, %2;" : "=f"(lo), "=f"(hi) : "l"(p))
#define DUP2(d, v) asm("mov.b64 %0, {%1, %1};" : "=l"(d) : "f"(v))

// ============================================================================
// K0: tiny bias precompute (also profiling-slot shifter)
// ============================================================================
__global__ void k_prep_bias(const float* __restrict__ bih, const float* __restrict__ bhh) {
    int t = threadIdx.x;
    g_bias[t] = bih[t] + bhh[t];
}

// ============================================================================
// K1 v2: price LSTM — 16 lanes per vertex (verified 8us)
// ============================================================================
__global__ void __launch_bounds__(256) k_price_lstm(
        const float* __restrict__ prices,
        const float* __restrict__ Wih, const float* __restrict__ Whh,
        const float* __restrict__ bih, const float* __restrict__ bhh) {
    __shared__ float sWT[1024];   // [u][j*4+gate]
    __shared__ float sWih[64], sb[64];
    int tid = threadIdx.x;
#pragma unroll
    for (int i = tid; i < 1024; i += 256) {
        int u = i >> 6, r = i & 63;
        int j = r >> 2, g = r & 3;
        sWT[i] = Whh[(g * 16 + j) * 16 + u];
    }
    if (tid < 64) { sWih[tid] = Wih[tid]; sb[tid] = bih[tid] + bhh[tid]; }
    __syncthreads();
    int lane = tid & 31, w = tid >> 5;
    int j = lane & 15, base = lane & 16;
    int v = blockIdx.x * 16 + w * 2 + (lane >> 4);
    float wih_i = sWih[j], wih_f = sWih[16 + j], wih_g = sWih[32 + j], wih_o = sWih[48 + j];
    float b_i = sb[j], b_f = sb[16 + j], b_g = sb[32 + j], b_o = sb[48 + j];
    float h = 0.f, c = 0.f;
#pragma unroll
    for (int t = 0; t < TT; t++) {
        float x = prices[t * VV + v];
        float gi = fmaf(wih_i, x, b_i);
        float gf = fmaf(wih_f, x, b_f);
        float gg = fmaf(wih_g, x, b_g);
        float go = fmaf(wih_o, x, b_o);
#pragma unroll
        for (int u = 0; u < 16; u++) {
            float hv = __shfl_sync(0xffffffffu, h, base + u);
            float4 wv = *(const float4*)&sWT[u * 64 + j * 4];
            gi = fmaf(wv.x, hv, gi);
            gf = fmaf(wv.y, hv, gf);
            gg = fmaf(wv.z, hv, gg);
            go = fmaf(wv.w, hv, go);
        }
        float cn = sigf(gf) * c + sigf(gi) * tanh_f(gg);
        c = cn;
        h = sigf(go) * tanh_f(cn);
        g_new_prices[(t * VV + v) * HH + j] = h;
    }
}

// ============================================================================
// K2 v6: VertexConv — warp = k-row pair, W rows in registers; regA rows
// padded to 10 ull (16B aligned) so mult-phase broadcast reads are 4xLDS128
// instead of 8xLDS64 (halves broadcast wavefronts).
// SMEM: regA [16e][32][10]ull 40960 | mlt [16e][32][33]f 67584 @40960 |
//       aA [16][33]f 2112 @108544 -> 110656 total
// ============================================================================
__global__ void __launch_bounds__(512, 1) k_vertex_conv(
        const int* __restrict__ he_members,
        const float* __restrict__ trans_w, const float* __restrict__ trans_b,
        const float* __restrict__ conv_w, const float* __restrict__ conv_b) {
    extern __shared__ char smv[];
    ull*   regA = (ull*)smv;                       // [16][320]
    float* mlt  = (float*)(smv + 40960);           // [16][1056]
    float* aA   = (float*)(smv + 108544);          // [16][33]
    __shared__ float s_cw[32];
    int tid = threadIdx.x, w = tid >> 5, lane = tid & 31;
    if (tid < 32) s_cw[tid] = conv_w[tid];
    float cb = conv_b[0];

    ull wreg[2][8];
    float tbv[2];
#pragma unroll
    for (int p = 0; p < 2; p++) {
        int m = (w + p * 16) * 32 + lane;
        const float4* src = (const float4*)(trans_w + m * 16);
        float4 v0 = src[0], v1 = src[1], v2 = src[2], v3 = src[3];
        ulonglong2 u0 = *(ulonglong2*)&v0, u1 = *(ulonglong2*)&v1;
        ulonglong2 u2 = *(ulonglong2*)&v2, u3 = *(ulonglong2*)&v3;
        wreg[p][0] = u0.x; wreg[p][1] = u0.y;
        wreg[p][2] = u1.x; wreg[p][3] = u1.y;
        wreg[p][4] = u2.x; wreg[p][5] = u2.y;
        wreg[p][6] = u3.x; wreg[p][7] = u3.y;
        tbv[p] = trans_b[m];
    }

    int ih = blockIdx.x * 16 + w;
    int t = ih >> 12;
    {
        int vidx = he_members[ih * KK + lane];
        const float2* src = (const float2*)(g_new_prices + (t * VV + vidx) * HH);
        ull* rw = regA + w * 320 + lane * 10;
#pragma unroll
        for (int d2 = 0; d2 < 8; d2++) {
            float2 v = src[d2];
            rw[d2] = *(ull*)&v;
        }
    }
    __syncthreads();

#pragma unroll
    for (int p = 0; p < 2; p++) {
        int k = w + p * 16;
#pragma unroll
        for (int e = 0; e < 16; e++) {
            const ulonglong2* rr = (const ulonglong2*)(regA + e * 320 + k * 10);
            ulonglong2 r01 = rr[0], r23 = rr[1], r45 = rr[2], r67 = rr[3];
            ull acc = 0ull;
            FMA2(acc, r01.x, wreg[p][0]);
            FMA2(acc, r01.y, wreg[p][1]);
            FMA2(acc, r23.x, wreg[p][2]);
            FMA2(acc, r23.y, wreg[p][3]);
            FMA2(acc, r45.x, wreg[p][4]);
            FMA2(acc, r45.y, wreg[p][5]);
            FMA2(acc, r67.x, wreg[p][6]);
            FMA2(acc, r67.y, wreg[p][7]);
            float lo, hi;
            UNPACK2(lo, hi, acc);
            mlt[e * 1056 + k * 33 + lane] = lo + hi + tbv[p];
        }
    }
    __syncthreads();

    {
        int e = w, k = lane;
        float* mrow = mlt + e * 1056 + k * 33;
        float r[32], mx = -1e30f;
#pragma unroll
        for (int j = 0; j < 32; j++) { r[j] = mrow[j]; mx = fmaxf(mx, r[j]); }
        float s = 0.f;
#pragma unroll
        for (int j = 0; j < 32; j++) { r[j] = __expf(r[j] - mx); s += r[j]; }
        float f = s_cw[k] / s;
#pragma unroll
        for (int j = 0; j < 32; j++) mrow[j] = r[j] * f;
    }
    __syncthreads();

    {
        float aj = 0.f;
#pragma unroll
        for (int k = 0; k < 32; k++) aj += mlt[w * 1056 + k * 33 + lane];
        aA[w * 33 + lane] = aj;
    }
    __syncwarp();
    if (lane < 16) {
        const float* regf = (const float*)(regA + w * 320);
        const float* aw = aA + w * 33;
        float acc = cb;
#pragma unroll
        for (int j = 0; j < 32; j++) acc = fmaf(aw[j], regf[j * 20 + lane], acc);
        g_he_emb[ih * HH + lane] = acc;
    }
}

// ============================================================================
// K3 (frozen, R15-measured 158.9us): FFMA2 GEMM, row-pair packing, M128,
// 256 threads, 8 rows/thread, single buffer, kk unroll 8.
// ============================================================================
__global__ void __launch_bounds__(256, 1) k_he_gemm(
        const float* __restrict__ node_embs,
        const float* __restrict__ W1, const float* __restrict__ Wm,
        const float* __restrict__ b1, const float* __restrict__ w2,
        const float* __restrict__ b2v) {
    extern __shared__ char smg[];
    float* wd   = (float*)smg;               // [16][340]
    float* a_s  = (float*)(smg + 21760);     // [16][132]
    float* sb1  = (float*)(smg + 30208);     // [196]
    float* sw2  = (float*)(smg + 30992);     // [196]
    float* zred = (float*)(smg + 31776);     // [128][17]

    int tid = threadIdx.x;
    int cg = tid & 15, rg = tid >> 4;
    int row0 = blockIdx.x * 128;

    if (tid < M1) { sb1[tid] = b1[tid]; sw2[tid] = w2[tid]; }

    const float4* wsrc[5]; uint32_t wbase[5]; int wmode[5];
#pragma unroll
    for (int i = 0; i < 5; i++) {
        int idx4 = tid + 256 * i;
        int m = idx4 >> 2, q = idx4 & 3;
        wmode[i] = (idx4 < 1040) ? 1 : 0;
        const float* s = (m < M1) ? (W1 + (size_t)m * CATD) : (Wm + (size_t)(m - M1) * CATD);
        wsrc[i] = (const float4*)s + q;
        if (m < 256) wbase[i] = (uint32_t)((q * 4) * WST + (m >> 4) * 20 + (m & 15));
        else         wbase[i] = (uint32_t)((q * 4) * WST + 320 + (m - 256));
    }
    const float4* asrc[2]; uint32_t abase[2];
#pragma unroll
    for (int i = 0; i < 2; i++) {
        int idx4 = tid + 256 * i;
        int r = idx4 >> 2, q = idx4 & 3;
        abase[i] = (uint32_t)((q * 4) * 132 + r);
        asrc[i] = (const float4*)(node_embs + (size_t)(row0 + r) * BERTD) + q;
    }

    float4 wpre[5], apre[2];
#pragma unroll
    for (int i = 0; i < 5; i++) {
        wpre[i] = make_float4(0.f, 0.f, 0.f, 0.f);
        if (wmode[i]) wpre[i] = *wsrc[i];
    }
#pragma unroll
    for (int i = 0; i < 2; i++) {
        int idx4 = tid + 256 * i;
        int r = idx4 >> 2, q = idx4 & 3;
        apre[i] = *((const float4*)(g_he_emb + (size_t)(row0 + r) * HH) + q);
    }

    ull acc[4][16], acct[4];
#pragma unroll
    for (int p = 0; p < 4; p++) {
        acct[p] = 0ull;
#pragma unroll
        for (int j = 0; j < 16; j++) acc[p][j] = 0ull;
    }

    for (int ch = 0; ch < 49; ch++) {
#pragma unroll
        for (int i = 0; i < 5; i++) {
            if (wmode[i]) {
                wd[wbase[i]]           = wpre[i].x;
                wd[wbase[i] + WST]     = wpre[i].y;
                wd[wbase[i] + 2 * WST] = wpre[i].z;
                wd[wbase[i] + 3 * WST] = wpre[i].w;
            }
        }
#pragma unroll
        for (int i = 0; i < 2; i++) {
            a_s[abase[i]]       = apre[i].x;
            a_s[abase[i] + 132] = apre[i].y;
            a_s[abase[i] + 264] = apre[i].z;
            a_s[abase[i] + 396] = apre[i].w;
        }
        __syncthreads();
        if (ch < 48) {
#pragma unroll
            for (int i = 0; i < 5; i++) {
                if (wmode[i]) { wpre[i] = wsrc[i][4]; wsrc[i] += 4; }
            }
            if (ch == 0) {
#pragma unroll
                for (int i = 0; i < 2; i++) apre[i] = asrc[i][0];
            } else {
#pragma unroll
                for (int i = 0; i < 2; i++) { apre[i] = asrc[i][4]; asrc[i] += 4; }
            }
        }
#pragma unroll 8
        for (int kk = 0; kk < 16; kk++) {
            const float* ab = a_s + kk * 132 + rg * 8;
            ulonglong2 au0 = *(const ulonglong2*)ab;
            ulonglong2 au1 = *(const ulonglong2*)(ab + 4);
            ull ap0 = au0.x, ap1 = au0.y, ap2 = au1.x, ap3 = au1.y;
            const float4* wrow = (const float4*)(wd + kk * WST + cg * 20);
            float4 wa = wrow[0], wb = wrow[1], wc = wrow[2], we = wrow[3];
#define COLFMA(J, WV) { ull wdp_; DUP2(wdp_, WV); \
            FMA2(acc[0][J], ap0, wdp_); FMA2(acc[1][J], ap1, wdp_); \
            FMA2(acc[2][J], ap2, wdp_); FMA2(acc[3][J], ap3, wdp_); }
            COLFMA(0,  wa.x) COLFMA(1,  wa.y) COLFMA(2,  wa.z) COLFMA(3,  wa.w)
            COLFMA(4,  wb.x) COLFMA(5,  wb.y) COLFMA(6,  wb.z) COLFMA(7,  wb.w)
            COLFMA(8,  wc.x) COLFMA(9,  wc.y) COLFMA(10, wc.z) COLFMA(11, wc.w)
            COLFMA(12, we.x) COLFMA(13, we.y) COLFMA(14, we.z) COLFMA(15, we.w)
#undef COLFMA
            float wtl = wd[kk * WST + 320 + cg];
            ull wdt; DUP2(wdt, wtl);
            FMA2(acct[0], ap0, wdt); FMA2(acct[1], ap1, wdt);
            FMA2(acct[2], ap2, wdt); FMA2(acct[3], ap3, wdt);
        }
        __syncthreads();
    }

    float zp[8];
#pragma unroll
    for (int rr = 0; rr < 8; rr++) zp[rr] = 0.f;
#pragma unroll
    for (int p = 0; p < 4; p++) {
#pragma unroll
        for (int j = 0; j < 16; j++) {
            int c = cg * 16 + j;
            float lo, hi;
            UNPACK2(lo, hi, acc[p][j]);
            if (c < M1) {
                zp[2 * p]     = fmaf(sw2[c], fmaxf(lo + sb1[c], 0.f), zp[2 * p]);
                zp[2 * p + 1] = fmaf(sw2[c], fmaxf(hi + sb1[c], 0.f), zp[2 * p + 1]);
            } else if (c < 260) {
                int r = row0 + rg * 8 + 2 * p;
                g_G[(size_t)r * 64 + (c - M1)]       = lo;
                g_G[(size_t)(r + 1) * 64 + (c - M1)] = hi;
            }
        }
        {
            int c = 256 + cg;
            if (c < 260) {
                float lo, hi;
                UNPACK2(lo, hi, acct[p]);
                int r = row0 + rg * 8 + 2 * p;
                g_G[(size_t)r * 64 + (c - M1)]       = lo;
                g_G[(size_t)(r + 1) * 64 + (c - M1)] = hi;
            }
        }
    }
#pragma unroll
    for (int rr = 0; rr < 8; rr++) zred[(rg * 8 + rr) * 17 + cg] = zp[rr];
    __syncthreads();
    if (tid < 128) {
        float s = b2v[0];
#pragma unroll
        for (int c = 0; c < 16; c++) s += zred[tid * 17 + c];
        g_z[row0 + tid] = s;
    }
}

// ============================================================================
// K4: per-vertex softmax over 8 edges + weighted sum of G rows -> gates.
// ============================================================================
__global__ void __launch_bounds__(256) k_gather_gates(const int* __restrict__ ve) {
    __shared__ float sbias[64];
    int tid = threadIdx.x;
    if (tid < 64) sbias[tid] = g_bias[tid];
    __syncthreads();
    int w = tid >> 5, lane = tid & 31;
    int tv = blockIdx.x * 8 + w;
    int t = tv >> 12;
    int eld = 0;
    if (lane < 8) eld = ve[tv * DD + lane];
    float zld = (lane < 8) ? g_z[t * EE + eld] : 0.f;
    float zv[8]; int ev[8];
#pragma unroll
    for (int d = 0; d < 8; d++) {
        zv[d] = __shfl_sync(0xffffffffu, zld, d);
        ev[d] = __shfl_sync(0xffffffffu, eld, d);
    }
    float mx = zv[0];
#pragma unroll
    for (int d = 1; d < 8; d++) mx = fmaxf(mx, zv[d]);
    float s = 0.f;
#pragma unroll
    for (int d = 0; d < 8; d++) { zv[d] = __expf(zv[d] - mx); s += zv[d]; }
    float inv = 1.f / s;
    float a0 = 0.f, a1 = 0.f;
#pragma unroll
    for (int d = 0; d < 8; d++) {
        const float* gr = g_G + (size_t)(t * EE + ev[d]) * 64;
        float wv = zv[d] * inv;
        a0 = fmaf(wv, gr[lane], a0);
        a1 = fmaf(wv, gr[lane + 32], a1);
    }
    g_gates[(size_t)tv * 64 + lane]      = a0 + sbias[lane];
    g_gates[(size_t)tv * 64 + lane + 32] = a1 + sbias[lane + 32];
}

// ============================================================================
// K5 v2: second LSTM + residual + attention + FC — 16 lanes per vertex
// ============================================================================
__global__ void __launch_bounds__(256) k_final(
        const float* __restrict__ Whh,
        const float* __restrict__ attn_in, const float* __restrict__ attn_out,
        const float* __restrict__ fc_w, const float* __restrict__ fc_b,
        float* __restrict__ out) {
    __shared__ float sWT[1024];     // [u][j*4+gate]
    __shared__ float sAinT[256];    // [u][j]
    __shared__ float sAoutT[512];   // [u(32)][j]
    __shared__ float sFc[32], sFcb[2];
    int tid = threadIdx.x;
#pragma unroll
    for (int i = tid; i < 1024; i += 256) {
        int u = i >> 6, r = i & 63;
        int j = r >> 2, g = r & 3;
        sWT[i] = Whh[(g * 16 + j) * 16 + u];
    }
    if (tid < 256) {
        int u = tid >> 4, j = tid & 15;
        sAinT[tid] = attn_in[j * 16 + u];
    }
#pragma unroll
    for (int i = tid; i < 512; i += 256) {
        int u = i >> 4, j = i & 15;
        sAoutT[i] = attn_out[j * 32 + u];
    }
    if (tid < 32) sFc[tid] = fc_w[tid];
    if (tid < 2) sFcb[tid] = fc_b[tid];
    __syncthreads();
    int lane = tid & 31, w = tid >> 5;
    int j = lane & 15, base = lane & 16;
    int v = blockIdx.x * 16 + w * 2 + (lane >> 4);
    float h = 0.f, c = 0.f, la[4];
#pragma unroll
    for (int t = 0; t < 4; t++) {
        size_t gb = (size_t)(t * VV + v) * 64;
        float gi = g_gates[gb + j];
        float gf = g_gates[gb + 16 + j];
        float gg = g_gates[gb + 32 + j];
        float go = g_gates[gb + 48 + j];
#pragma unroll
        for (int u = 0; u < 16; u++) {
            float hv = __shfl_sync(0xffffffffu, h, base + u);
            float4 wv = *(const float4*)&sWT[u * 64 + j * 4];
            gi = fmaf(wv.x, hv, gi);
            gf = fmaf(wv.y, hv, gf);
            gg = fmaf(wv.z, hv, gg);
            go = fmaf(wv.w, hv, go);
        }
        float cn = sigf(gf) * c + sigf(gi) * tanh_f(gg);
        c = cn;
        h = sigf(go) * tanh_f(cn);
        la[t] = h + g_new_prices[(t * VV + v) * HH + j];
    }
    float q = 0.f;
#pragma unroll
    for (int u = 0; u < 16; u++) {
        float la3u = __shfl_sync(0xffffffffu, la[3], base + u);
        q = fmaf(sAinT[u * 16 + j], la3u, q);
    }
    float sc[4];
#pragma unroll
    for (int t = 0; t < 4; t++) {
        float p = q * la[t];
#pragma unroll
        for (int m = 8; m; m >>= 1) p += __shfl_xor_sync(0xffffffffu, p, m);
        sc[t] = p;
    }
    float mx = fmaxf(fmaxf(sc[0], sc[1]), fmaxf(sc[2], sc[3]));
    float ssum = 0.f;
#pragma unroll
    for (int t = 0; t < 4; t++) { sc[t] = __expf(sc[t] - mx); ssum += sc[t]; }
    float inv = 1.f / ssum;
    float mix = 0.f;
#pragma unroll
    for (int t = 0; t < 4; t++) mix = fmaf(sc[t] * inv, la[t], mix);
    float a = 0.f;
#pragma unroll
    for (int u = 0; u < 16; u++) {
        float mu = __shfl_sync(0xffffffffu, mix, base + u);
        float qu = __shfl_sync(0xffffffffu, q, base + u);
        a = fmaf(sAoutT[u * 16 + j], mu, a);
        a = fmaf(sAoutT[(16 + u) * 16 + j], qu, a);
    }
    float attnj = tanh_f(a);
    float p0 = sFc[j] * attnj, p1 = sFc[16 + j] * attnj;
#pragma unroll
    for (int m = 8; m; m >>= 1) {
        p0 += __shfl_xor_sync(0xffffffffu, p0, m);
        p1 += __shfl_xor_sync(0xffffffffu, p1, m);
    }
    if (j == 0) {
        out[v * 2]     = p0 + sFcb[0];
        out[v * 2 + 1] = p1 + sFcb[1];
    }
}

// ============================================================================
extern "C" void kernel_launch(void* const* d_in, const int* in_sizes, int n_in,
                              void* d_out, int out_size) {
    const float* prices = (const float*)d_in[0];
    const float* node   = (const float*)d_in[1];
    const int*   he_mem = (const int*)d_in[2];
    const int*   ve     = (const int*)d_in[3];
    const float* Wih_p  = (const float*)d_in[4];
    const float* Whh_p  = (const float*)d_in[5];
    const float* bih_p  = (const float*)d_in[6];
    const float* bhh_p  = (const float*)d_in[7];
    const float* Wih_m  = (const float*)d_in[8];
    const float* Whh_m  = (const float*)d_in[9];
    const float* bih_m  = (const float*)d_in[10];
    const float* bhh_m  = (const float*)d_in[11];
    const float* tw     = (const float*)d_in[12];
    const float* tb     = (const float*)d_in[13];
    const float* cw     = (const float*)d_in[14];
    const float* cbv    = (const float*)d_in[15];
    const float* w1     = (const float*)d_in[16];
    const float* b1     = (const float*)d_in[17];
    const float* w2     = (const float*)d_in[18];
    const float* b2     = (const float*)d_in[19];
    const float* ain    = (const float*)d_in[20];
    const float* aout   = (const float*)d_in[21];
    const float* fcw    = (const float*)d_in[22];
    const float* fcb    = (const float*)d_in[23];
    float* out = (float*)d_out;
    (void)in_sizes; (void)n_in; (void)out_size;

    const int smem_vc = 110656;
    const int smem_ge = 40480;
    cudaFuncSetAttribute(k_vertex_conv, cudaFuncAttributeMaxDynamicSharedMemorySize, smem_vc);
    cudaFuncSetAttribute(k_he_gemm, cudaFuncAttributeMaxDynamicSharedMemorySize, smem_ge);

    k_prep_bias<<<1, 64>>>(bih_m, bhh_m);                                   // 0
    k_price_lstm<<<VV / 16, 256>>>(prices, Wih_p, Whh_p, bih_p, bhh_p);     // 1
    k_prep_bias<<<1, 64>>>(bih_m, bhh_m);                                   // 2 (slot shifter)
    k_vertex_conv<<<TT * EE / 16, 512, smem_vc>>>(he_mem, tw, tb, cw, cbv); // 3 <- profiled
    k_he_gemm<<<NROWS / 128, 256, smem_ge>>>(node, w1, Wih_m, b1, w2, b2);  // 4
    k_gather_gates<<<TT * VV / 8, 256>>>(ve);                               // 5
    k_final<<<VV / 16, 256>>>(Whh_m, ain, aout, fcw, fcb, out);             // 6
}